// round 1
// baseline (speedup 1.0000x reference)
#include <cuda_runtime.h>
#include <cstdint>

// Problem constants
#define SDIM   64           // spatial w
#define HDIM   63           // d dimension (S-1)
#define BDIM   32
#define OC     256          // channels per layer (in == out == 256)
#define STRIDE 72           // smem row stride in floats (bank-conflict-free: 72 % 32 == 8)
#define SMEM_BYTES (2 * 256 * STRIDE * 4)   // two activation buffers = 147456 B

// Pre-converted TF32 weights (rounded with cvt.rna once per launch)
__device__ float g_Wt[3 * 65536];

__device__ __forceinline__ float tf32r(float x) {
    uint32_t u;
    asm("cvt.rna.tf32.f32 %0, %1;" : "=r"(u) : "f"(x));
    return __uint_as_float(u);
}

__global__ void convert_w_kernel(const float* __restrict__ W1,
                                 const float* __restrict__ W2,
                                 const float* __restrict__ W3) {
    int i = blockIdx.x * blockDim.x + threadIdx.x;   // 65536 threads
    g_Wt[i]          = tf32r(W1[i]);
    g_Wt[65536 + i]  = tf32r(W2[i]);
    g_Wt[131072 + i] = tf32r(W3[i]);
}

__device__ __forceinline__ void mma_tf32(float* d, const uint32_t* a,
                                         uint32_t b0, uint32_t b1) {
    asm volatile(
        "mma.sync.aligned.m16n8k8.row.col.f32.tf32.tf32.f32 "
        "{%0,%1,%2,%3}, {%4,%5,%6,%7}, {%8,%9}, {%0,%1,%2,%3};"
        : "+f"(d[0]), "+f"(d[1]), "+f"(d[2]), "+f"(d[3])
        : "r"(a[0]), "r"(a[1]), "r"(a[2]), "r"(a[3]), "r"(b0), "r"(b1));
}

// One block per (b, h): tile = 256 outputs x 64 positions, 3 layers fused.
__global__ __launch_bounds__(256, 1) void fused_kernel(
    const float* __restrict__ x,      // (32, 64, 64)
    const float* __restrict__ xc,     // (32, 128, 63, 64)
    const float* __restrict__ bias1,
    const float* __restrict__ bias2,
    const float* __restrict__ bias3,
    float* __restrict__ out)          // (32, 256, 63, 64)
{
    extern __shared__ float smem[];
    float* bufA = smem;
    float* bufB = smem + 256 * STRIDE;

    const int tid  = threadIdx.x;
    const int lane = tid & 31;
    const int warp = tid >> 5;
    const int bh = blockIdx.x;
    const int b = bh / HDIM;
    const int h = bh % HDIM;

    // ---- Build the 256-channel input tile: rows k, cols w (tf32-rounded) ----
    {
        const int w0 = lane * 2;
        for (int k = warp; k < 256; k += 8) {
            float v0, v1;
            if (k < 128) {
                const float* p = xc + (((size_t)(b * 128 + k)) * HDIM + h) * SDIM;
                v0 = p[w0]; v1 = p[w0 + 1];
            } else if (k < 192) {
                const float* p = x + ((size_t)(b * 64 + (k - 128))) * SDIM;
                v0 = p[w0]; v1 = p[w0 + 1];
            } else {
                // rolled: x[b, c, (w - (h+1)) mod 64]
                const float* p = x + ((size_t)(b * 64 + (k - 192))) * SDIM;
                v0 = p[(w0 - h - 1) & 63];
                v1 = p[(w0 - h) & 63];
            }
            bufA[k * STRIDE + w0]     = tf32r(v0);
            bufA[k * STRIDE + w0 + 1] = tf32r(v1);
        }
    }
    __syncthreads();

    const int g = lane >> 2;      // groupID   (0..7)
    const int t = lane & 3;       // thread-in-group (0..3)
    const int obase = warp * 32;  // this warp's 32-output slice
    const int sb = t * STRIDE + g;  // B-fragment smem word offset base

    const float* biases[3] = {bias1, bias2, bias3};

    #pragma unroll
    for (int l = 0; l < 3; l++) {
        const float* Wl  = g_Wt + l * 65536;
        const float* src = (l & 1) ? bufB : bufA;
        float*       dst = (l & 1) ? bufA : bufB;
        const uint32_t* su = (const uint32_t*)src;

        float acc[2][8][4];
        #pragma unroll
        for (int mt = 0; mt < 2; mt++)
            #pragma unroll
            for (int nt = 0; nt < 8; nt++)
                #pragma unroll
                for (int r = 0; r < 4; r++) acc[mt][nt][r] = 0.f;

        #pragma unroll 4
        for (int kk = 0; kk < 256; kk += 8) {
            uint32_t a[2][4];
            #pragma unroll
            for (int mt = 0; mt < 2; mt++) {
                const float* p = Wl + (size_t)(obase + mt * 16 + g) * 256 + t + kk;
                a[mt][0] = __float_as_uint(p[0]);        // row g,    col t
                a[mt][1] = __float_as_uint(p[2048]);     // row g+8,  col t
                a[mt][2] = __float_as_uint(p[4]);        // row g,    col t+4
                a[mt][3] = __float_as_uint(p[2052]);     // row g+8,  col t+4
            }
            #pragma unroll
            for (int nt = 0; nt < 8; nt++) {
                uint32_t b0 = su[kk * STRIDE + sb + nt * 8];         // act[kk+t][nt*8+g]
                uint32_t b1 = su[(kk + 4) * STRIDE + sb + nt * 8];   // act[kk+4+t][..]
                mma_tf32(acc[0][nt], a[0], b0, b1);
                mma_tf32(acc[1][nt], a[1], b0, b1);
            }
        }

        const float* bl = biases[l];
        if (l < 2) {
            #pragma unroll
            for (int mt = 0; mt < 2; mt++) {
                int r0 = obase + mt * 16 + g;
                float bb0 = bl[r0], bb8 = bl[r0 + 8];
                #pragma unroll
                for (int nt = 0; nt < 8; nt++) {
                    int p0 = nt * 8 + 2 * t;
                    dst[r0 * STRIDE + p0]           = tf32r(fmaxf(acc[mt][nt][0] + bb0, 0.f));
                    dst[r0 * STRIDE + p0 + 1]       = tf32r(fmaxf(acc[mt][nt][1] + bb0, 0.f));
                    dst[(r0 + 8) * STRIDE + p0]     = tf32r(fmaxf(acc[mt][nt][2] + bb8, 0.f));
                    dst[(r0 + 8) * STRIDE + p0 + 1] = tf32r(fmaxf(acc[mt][nt][3] + bb8, 0.f));
                }
            }
            __syncthreads();
        } else {
            // out[((b*256 + o)*63 + h)*64 + w]
            float* ob = out + (size_t)b * (256 * HDIM * SDIM) + (size_t)h * SDIM;
            #pragma unroll
            for (int mt = 0; mt < 2; mt++) {
                int r0 = obase + mt * 16 + g;
                float bb0 = bl[r0], bb8 = bl[r0 + 8];
                #pragma unroll
                for (int nt = 0; nt < 8; nt++) {
                    int p0 = nt * 8 + 2 * t;
                    float2 v0 = make_float2(fmaxf(acc[mt][nt][0] + bb0, 0.f),
                                            fmaxf(acc[mt][nt][1] + bb0, 0.f));
                    float2 v1 = make_float2(fmaxf(acc[mt][nt][2] + bb8, 0.f),
                                            fmaxf(acc[mt][nt][3] + bb8, 0.f));
                    *(float2*)(ob + (size_t)r0 * (HDIM * SDIM) + p0)       = v0;
                    *(float2*)(ob + (size_t)(r0 + 8) * (HDIM * SDIM) + p0) = v1;
                }
            }
        }
    }
}

extern "C" void kernel_launch(void* const* d_in, const int* in_sizes, int n_in,
                              void* d_out, int out_size) {
    // Robust input mapping by element count (dict order: x, xc, W1,b1, W2,b2, W3,b3, scalars)
    const float* x = nullptr;
    const float* xc = nullptr;
    const float* Ws[3] = {nullptr, nullptr, nullptr};
    const float* Bs[3] = {nullptr, nullptr, nullptr};
    int wi = 0, bi = 0;
    for (int i = 0; i < n_in; i++) {
        int sz = in_sizes[i];
        if (sz == 32 * 64 * 64)            x = (const float*)d_in[i];
        else if (sz == 32 * 128 * 63 * 64) xc = (const float*)d_in[i];
        else if (sz == 256 * 256 && wi < 3) Ws[wi++] = (const float*)d_in[i];
        else if (sz == 256 && bi < 3)       Bs[bi++] = (const float*)d_in[i];
    }
    float* out = (float*)d_out;

    convert_w_kernel<<<256, 256>>>(Ws[0], Ws[1], Ws[2]);

    cudaFuncSetAttribute(fused_kernel,
                         cudaFuncAttributeMaxDynamicSharedMemorySize, SMEM_BYTES);
    fused_kernel<<<BDIM * HDIM, 256, SMEM_BYTES>>>(x, xc, Bs[0], Bs[1], Bs[2], out);
}